// round 6
// baseline (speedup 1.0000x reference)
#include <cuda_runtime.h>

#define N_  64
#define T_  4096
#define D_  128
#define CH  16
#define TCH (T_/CH)   // 256 timesteps per chunk; 32 per warp

// Scratch (no allocations allowed anywhere)
__device__ float g_partial[N_ * CH * D_];    // 512 KB
__device__ float g_chunksum[N_ * CH];        // 4 KB
__device__ int   g_ticket[N_];               // zero-init; finisher resets -> graph-replay safe

// ---------------------------------------------------------------------------
// Fused kernel: block (n, c) handles t in [c*TCH, (c+1)*TCH):
//   w = exp( (t<len[n]) * <key[t,n,:], q[n,:]> )   (no max-sub: |dot| << 88,
//   softmax cancels any shift exactly)
//   acc[d] += w * value[t,n,d] ;  ws += w
// Four per-t dots computed first, THEN 4 independent butterfly chains run
// stage-interleaved (SHFL-pipe ILP). Dual FMA accumulators break the
// accumulation dependency. Last block per n reduces + normalizes.
// All sums in fixed index order -> deterministic.
// ---------------------------------------------------------------------------
__global__ void __launch_bounds__(256) fused_attn_kernel(
    const float* __restrict__ q,
    const float* __restrict__ key,
    const float* __restrict__ value,
    const int* __restrict__ slen,          // int32 on device (JAX x64 off)
    float* __restrict__ out_ctx,
    float* __restrict__ mask_out)
{
    const int n    = blockIdx.x;           // fast index -> concurrent blocks
    const int c    = blockIdx.y;           //   span all n for one t-window
    const int lane = threadIdx.x & 31;
    const int wp   = threadIdx.x >> 5;
    const int len  = slen[n];

    // Coalesced streaming mask write: 1KB per block, write-once data
    {
        const int t = c * TCH + threadIdx.x;
        __stcs(&mask_out[(size_t)n * T_ + t], (t < len) ? 1.0f : 0.0f);
    }

    const float4 qv = reinterpret_cast<const float4*>(q + (size_t)n * D_)[lane];
    const float4* __restrict__ k4 = reinterpret_cast<const float4*>(key);
    const float4* __restrict__ v4 = reinterpret_cast<const float4*>(value);

    const size_t strideT = (size_t)N_ * (D_ / 4);            // per-t stride (float4)
    const int    tbase   = c * TCH + wp * 32;                // this warp's first t
    const size_t idx0    = ((size_t)tbase * N_ + n) * (D_ / 4) + lane;

    float4 acc0 = make_float4(0.f, 0.f, 0.f, 0.f);
    float4 acc1 = make_float4(0.f, 0.f, 0.f, 0.f);
    float  ws0 = 0.0f, ws1 = 0.0f;

#pragma unroll
    for (int i = 0; i < 32; i += 4) {
        float4 kv0, kv1, kv2, kv3, vv0, vv1, vv2, vv3;
        {
            const size_t o0 = idx0 + (size_t)(i + 0) * strideT;
            const size_t o1 = idx0 + (size_t)(i + 1) * strideT;
            const size_t o2 = idx0 + (size_t)(i + 2) * strideT;
            const size_t o3 = idx0 + (size_t)(i + 3) * strideT;
            kv0 = k4[o0];  kv1 = k4[o1];  kv2 = k4[o2];  kv3 = k4[o3];
            vv0 = v4[o0];  vv1 = v4[o1];  vv2 = v4[o2];  vv3 = v4[o3];
        }

        // per-lane partial dots (independent)
        float p0 = kv0.x*qv.x + kv0.y*qv.y + kv0.z*qv.z + kv0.w*qv.w;
        float p1 = kv1.x*qv.x + kv1.y*qv.y + kv1.z*qv.z + kv1.w*qv.w;
        float p2 = kv2.x*qv.x + kv2.y*qv.y + kv2.z*qv.z + kv2.w*qv.w;
        float p3 = kv3.x*qv.x + kv3.y*qv.y + kv3.z*qv.z + kv3.w*qv.w;

        // stage-interleaved butterflies: 4 independent chains in the SHFL pipe
#pragma unroll
        for (int s = 16; s > 0; s >>= 1) {
            p0 += __shfl_xor_sync(0xffffffffu, p0, s);
            p1 += __shfl_xor_sync(0xffffffffu, p1, s);
            p2 += __shfl_xor_sync(0xffffffffu, p2, s);
            p3 += __shfl_xor_sync(0xffffffffu, p3, s);
        }

        const float w0 = __expf((tbase + i + 0 < len) ? p0 : 0.0f);
        const float w1 = __expf((tbase + i + 1 < len) ? p1 : 0.0f);
        const float w2 = __expf((tbase + i + 2 < len) ? p2 : 0.0f);
        const float w3 = __expf((tbase + i + 3 < len) ? p3 : 0.0f);

        ws0 += w0 + w1;
        ws1 += w2 + w3;
        acc0.x += w0*vv0.x;  acc0.y += w0*vv0.y;  acc0.z += w0*vv0.z;  acc0.w += w0*vv0.w;
        acc1.x += w1*vv1.x;  acc1.y += w1*vv1.y;  acc1.z += w1*vv1.z;  acc1.w += w1*vv1.w;
        acc0.x += w2*vv2.x;  acc0.y += w2*vv2.y;  acc0.z += w2*vv2.z;  acc0.w += w2*vv2.w;
        acc1.x += w3*vv3.x;  acc1.y += w3*vv3.y;  acc1.z += w3*vv3.z;  acc1.w += w3*vv3.w;
    }

    // combine dual accumulators
    float4 acc = make_float4(acc0.x + acc1.x, acc0.y + acc1.y,
                             acc0.z + acc1.z, acc0.w + acc1.w);
    const float ws = ws0 + ws1;

    // Cross-warp reduce (fixed order -> deterministic)
    __shared__ float4 red[8][32];
    __shared__ float  wsum[8];
    __shared__ int    isLast;
    red[wp][lane] = acc;
    if (lane == 0) wsum[wp] = ws;
    __syncthreads();

    if (wp == 0) {
        float4 s = red[0][lane];
#pragma unroll
        for (int k = 1; k < 8; k++) {
            const float4 r = red[k][lane];
            s.x += r.x;  s.y += r.y;  s.z += r.z;  s.w += r.w;
        }
        __stcg(&reinterpret_cast<float4*>(
                   g_partial + ((size_t)n * CH + c) * D_)[lane], s);
        if (lane == 0) {
            float t = 0.0f;
#pragma unroll
            for (int k = 0; k < 8; k++) t += wsum[k];
            __stcg(&g_chunksum[n * CH + c], t);
        }
        __threadfence();   // make this warp's partial/chunksum globally visible
    }
    __syncthreads();

    // Completion ticket: last block for this n does the final reduce.
    if (threadIdx.x == 0)
        isLast = (atomicAdd(&g_ticket[n], 1) == CH - 1) ? 1 : 0;
    __syncthreads();

    if (isLast) {
        if (threadIdx.x < D_) {
            const int d = threadIdx.x;
            float rs = 0.0f;
#pragma unroll
            for (int k = 0; k < CH; k++)
                rs += __ldcg(&g_chunksum[n * CH + k]);      // L1-bypass: other CTAs' data
            float s = 0.0f;
#pragma unroll
            for (int k = 0; k < CH; k++)
                s += __ldcg(&g_partial[((size_t)n * CH + k) * D_ + d]);
            out_ctx[(size_t)n * D_ + d] = s / rs;
        }
        if (threadIdx.x == 0) g_ticket[n] = 0;   // reset for next replay
    }
}

// ---------------------------------------------------------------------------
extern "C" void kernel_launch(void* const* d_in, const int* in_sizes, int n_in,
                              void* d_out, int out_size)
{
    const float* query = (const float*)d_in[0];
    const float* key   = (const float*)d_in[1];
    const float* value = (const float*)d_in[2];
    const int*   slen  = (const int*)d_in[3];   // int32 on device (JAX x64 off)

    float* out_ctx  = (float*)d_out;           // (N, D)
    float* out_mask = (float*)d_out + N_ * D_; // (N, T)

    dim3 g(N_, CH);   // n fastest -> concurrent CTAs read contiguous windows
    fused_attn_kernel<<<g, 256>>>(query, key, value, slen, out_ctx, out_mask);
}